// round 6
// baseline (speedup 1.0000x reference)
#include <cuda_runtime.h>
#include <cstdint>

// ---------------------------------------------------------------------------
// SimpleLSTM on GB300 (sm_103a) — round 6: round-5 structure + cluster
// mbarrier signaling (data stays in L2; flags move to DSMEM mbarriers).
//
//   kernel 1 (table_kernel): token table T[v][g] = E[v] . W_x^T + b for the
//       768 LIVE gate rows (F, O, Htmp; I gate is dead). f32x2 inner product.
//   kernel 2 (lstm_kernel): 16 clusters x 8 CTAs (cluster = batch group of 8
//       rows; rank = 32-col hidden tile). Warp kq consumes exactly the H
//       slice produced by rank kq: it sleeps on local mbar[kq] (TRYWAIT) and
//       ld.cg's its 8x32 slice from the global H double buffer. Producers
//       signal with one remote release-arrive per peer. Self slice (kq==ct)
//       is copied from locally staged SMEM, no L2.
// ---------------------------------------------------------------------------

#define NB    128
#define LSEQ  2048
#define HDIM  256
#define EMB   256
#define VOC   32000
#define G3    768
#define NT    256

__device__ float g_T[VOC * G3];          // token-gate table (~98.3 MB)
__device__ float g_Hbuf[2][NB * HDIM];   // H double buffer

// ---------------------------------------------------------------------------
// helpers
// ---------------------------------------------------------------------------
__device__ __forceinline__ unsigned long long ffma2(unsigned long long a,
                                                    unsigned long long b,
                                                    unsigned long long c)
{
    unsigned long long d;
    asm("fma.rn.f32x2 %0, %1, %2, %3;" : "=l"(d) : "l"(a), "l"(b), "l"(c));
    return d;
}

__device__ __forceinline__ unsigned long long packf2(float lo, float hi)
{
    unsigned long long v;
    asm("mov.b64 %0, {%1, %2};" : "=l"(v) : "f"(lo), "f"(hi));
    return v;
}

__device__ __forceinline__ float f2sum(unsigned long long v)
{
    float2 f;
    asm("mov.b64 {%0, %1}, %2;" : "=f"(f.x), "=f"(f.y) : "l"(v));
    return f.x + f.y;
}

__device__ __forceinline__ uint32_t smem_u32(const void* p)
{
    uint32_t a;
    asm("{ .reg .u64 t; cvta.to.shared.u64 t, %1; cvt.u32.u64 %0, t; }"
        : "=r"(a) : "l"(p));
    return a;
}

__device__ __forceinline__ uint32_t ctarank()
{
    uint32_t r;
    asm("mov.u32 %0, %%cluster_ctarank;" : "=r"(r));
    return r;
}

__device__ __forceinline__ void mbar_init(uint32_t addr, uint32_t count)
{
    asm volatile("mbarrier.init.shared.b64 [%0], %1;" :: "r"(addr), "r"(count)
                 : "memory");
}

// release-arrive on the same-offset mbarrier in cluster CTA `rank`
__device__ __forceinline__ void mbar_arrive_rank(uint32_t laddr, uint32_t rank)
{
    asm volatile(
        "{ .reg .b32 ra; mapa.shared::cluster.u32 ra, %0, %1;\n\t"
        "  mbarrier.arrive.release.cluster.shared::cluster.b64 _, [ra]; }"
        :: "r"(laddr), "r"(rank) : "memory");
}

// sleep-wait on a LOCAL mbarrier with acquire at cluster scope
__device__ __forceinline__ void mbar_wait_parity(uint32_t addr, uint32_t parity)
{
    uint32_t done = 0;
    while (!done) {
        asm volatile(
            "{ .reg .pred p;\n\t"
            "  mbarrier.try_wait.parity.acquire.cluster.shared::cta.b64 p, [%1], %2, 0x989680;\n\t"
            "  selp.b32 %0, 1, 0, p; }"
            : "=r"(done) : "r"(addr), "r"(parity) : "memory");
    }
}

__device__ __forceinline__ void cluster_sync_()
{
    asm volatile("barrier.cluster.arrive.aligned;" ::: "memory");
    asm volatile("barrier.cluster.wait.aligned;" ::: "memory");
}

__device__ __forceinline__ float sig_fast(float x)
{
    return __fdividef(1.0f, 1.0f + __expf(-x));
}

__device__ __forceinline__ float tanh_fast(float x)
{
    return __fdividef(2.0f, 1.0f + __expf(-2.0f * x)) - 1.0f;
}

// ---------------------------------------------------------------------------
// Kernel 1: token table GEMM (M=32000, N=768 live gates, K=256)
// ---------------------------------------------------------------------------
__global__ void table_kernel(const float* __restrict__ E,
                             const float* __restrict__ Ww,
                             const float* __restrict__ Wb)
{
    __shared__ float Esm[32][68];
    __shared__ float Wsm[32][68];

    const int tid = threadIdx.x;
    const int v0  = blockIdx.x * 64;
    const int g0  = blockIdx.y * 64;

    const int tx = tid & 15;
    const int ty = tid >> 4;

    unsigned long long acc2[4][2];
#pragma unroll
    for (int i = 0; i < 4; i++) { acc2[i][0] = 0ull; acc2[i][1] = 0ull; }

    for (int kb = 0; kb < 8; kb++) {
        for (int i = tid; i < 64 * 32; i += 256) {
            int row = i >> 5, kk = i & 31;
            Esm[kk][row] = E[(v0 + row) * EMB + kb * 32 + kk];
            int gg   = g0 + row;
            int gate = gg >> 8, jj = gg & 255;
            int grow = (gate == 0 ? 0 : (gate == 1 ? 512 : 768)) + jj;
            Wsm[kk][row] = Ww[grow * 512 + 256 + kb * 32 + kk];
        }
        __syncthreads();
#pragma unroll
        for (int kk = 0; kk < 32; kk++) {
            float4 a4 = *(const float4*)&Esm[kk][ty * 4];
            float4 b4 = *(const float4*)&Wsm[kk][tx * 4];
            unsigned long long blo = packf2(b4.x, b4.y);
            unsigned long long bhi = packf2(b4.z, b4.w);
            float av[4] = {a4.x, a4.y, a4.z, a4.w};
#pragma unroll
            for (int i = 0; i < 4; i++) {
                unsigned long long aa = packf2(av[i], av[i]);
                acc2[i][0] = ffma2(aa, blo, acc2[i][0]);
                acc2[i][1] = ffma2(aa, bhi, acc2[i][1]);
            }
        }
        __syncthreads();
    }

#pragma unroll
    for (int i = 0; i < 4; i++) {
        int v = v0 + ty * 4 + i;
#pragma unroll
        for (int jp = 0; jp < 2; jp++) {
            float2 f;
            asm("mov.b64 {%0, %1}, %2;" : "=f"(f.x), "=f"(f.y) : "l"(acc2[i][jp]));
            float fv[2] = {f.x, f.y};
#pragma unroll
            for (int s = 0; s < 2; s++) {
                int g    = g0 + tx * 4 + jp * 2 + s;
                int gate = g >> 8, jj = g & 255;
                int grow = (gate == 0 ? 0 : (gate == 1 ? 512 : 768)) + jj;
                g_T[v * G3 + g] = fv[s] + Wb[grow];
            }
        }
    }
}

// ---------------------------------------------------------------------------
// Kernel 2: clustered persistent recurrence (flags via mbarrier, data via L2).
// ---------------------------------------------------------------------------

// dynamic SMEM layout (bytes)
#define SM_W     0         // float4 Wsm[(k4*3+gate)*32 + j]   : 98304
#define SM_H     98304     // float4 Hsm[r*64 + k4]             : 8192
#define SM_G     106496    // float  Gsm[((kq*3+g)*8+r)*32+j]   : 24576
#define SM_C     131072    // float  Csm[256]                   : 1024
#define SM_HS    132096    // float  Hstage[256]                : 1024
#define SM_TOK   133120    // int    tokb[2][8]                 : 64
#define SM_MBAR  133184    // uint64 mbar[8]                    : 64
#define SMEM_TOTAL 133248

__global__ void __launch_bounds__(NT, 1) __cluster_dims__(8, 1, 1)
lstm_kernel(const void* __restrict__ Xraw,
            const float* __restrict__ Ww,
            float* __restrict__ out)
{
    extern __shared__ char smem[];
    float4*           Wsm4    = (float4*)(smem + SM_W);
    const ulonglong2* Wsm     = (const ulonglong2*)(smem + SM_W);
    float4*           Hsm4    = (float4*)(smem + SM_H);
    const ulonglong2* Hsm     = (const ulonglong2*)(smem + SM_H);
    float*            Gsm     = (float*)(smem + SM_G);
    float*            Csm     = (float*)(smem + SM_C);
    float*            Hstage  = (float*)(smem + SM_HS);
    const float4*     Hstage4 = (const float4*)(smem + SM_HS);
    int*              tokb    = (int*)(smem + SM_TOK);

    const uint32_t sbase = smem_u32(smem);

    const int tid  = threadIdx.x;
    const int ct   = (int)ctarank();       // 0..7: hidden col tile
    const int bt   = blockIdx.x >> 3;      // 0..15: batch group (cluster id)
    const int rb   = bt * 8;
    const int j0   = ct * 32;

    const int kq   = tid >> 5;             // k-slice / producer rank
    const int lane = tid & 31;

    // --- int64 vs int32 token buffer detection ----------------------------
    const int* Xi = (const int*)Xraw;
    bool is64 = true;
#pragma unroll
    for (int i = 0; i < 16; i++)
        if (Xi[2 * i + 1] != 0) is64 = false;
    const long long* Xl = (const long long*)Xraw;

    // --- load W slice: Wsm[(k4*3+gate)*32 + j] -----------------------------
    for (int i = tid; i < 96 * 64; i += NT) {
        int row = i >> 6, k4 = i & 63;
        int gate = row >> 5, j = row & 31;
        int grow = (gate == 0 ? 0 : (gate == 1 ? 512 : 768)) + j0 + j;
        Wsm4[(k4 * 3 + gate) * 32 + j] = *(const float4*)(Ww + grow * 512 + k4 * 4);
    }
    Csm[tid] = 0.0f;
    for (int i = tid; i < 512; i += NT)     // Hsm zero (used at t=0)
        Hsm4[i] = make_float4(0.f, 0.f, 0.f, 0.f);
    if (tid < 8) {
        tokb[tid] = is64 ? (int)Xl[(rb + tid) * LSEQ] : Xi[(rb + tid) * LSEQ];
        mbar_init(sbase + SM_MBAR + (uint32_t)tid * 8, 1);
    }
    __syncthreads();
    cluster_sync_();   // all mbarriers initialized before any remote arrive

    // per-lane H slice mapping
    const int r0 = lane >> 3,        q0 = lane & 7;
    const int r1 = (lane + 32) >> 3, q1 = lane & 7;

    for (int t = 0; t < LSEQ; t++) {
        const int cur = t & 1, nxt = cur ^ 1;

        // ---- Gx prefetch (token-determined; overlaps the wait) ------------
        const int er = kq, ej = lane;
        const float* Tr = g_T + (long long)tokb[cur * 8 + er] * G3 + j0 + ej;
        float gxF = __ldg(Tr);
        float gxO = __ldg(Tr + 256);
        float gxH = __ldg(Tr + 512);

        if (tid < 8 && t + 1 < LSEQ)
            tokb[nxt * 8 + tid] = is64 ? (int)Xl[(rb + tid) * LSEQ + t + 1]
                                       : Xi[(rb + tid) * LSEQ + t + 1];

        // ---- per-warp: wait for producer rank kq, load 8x32 H slice -------
        if (t > 0) {
            if (kq == ct) {
                // self slice staged locally last step (ordered by sync B)
                Hsm4[r0 * 64 + kq * 8 + q0] = Hstage4[r0 * 8 + q0];
                Hsm4[r1 * 64 + kq * 8 + q1] = Hstage4[r1 * 8 + q1];
            } else {
                mbar_wait_parity(sbase + SM_MBAR + (uint32_t)kq * 8,
                                 (unsigned)(t - 1) & 1u);
                const float* hb = g_Hbuf[cur];
                float4 v0 = __ldcg((const float4*)(hb + (rb + r0) * HDIM + kq * 32 + q0 * 4));
                float4 v1 = __ldcg((const float4*)(hb + (rb + r1) * HDIM + kq * 32 + q1 * 4));
                Hsm4[r0 * 64 + kq * 8 + q0] = v0;
                Hsm4[r1 * 64 + kq * 8 + q1] = v1;
            }
            __syncwarp();
        }

        // ---- k-loop: this warp's k-slice, 3 gates, 8 rows ------------------
        unsigned long long aF[8], aO[8], aH[8];
#pragma unroll
        for (int r = 0; r < 8; r++) { aF[r] = 0ull; aO[r] = 0ull; aH[r] = 0ull; }

        const int kb = kq * 8;
#pragma unroll 4
        for (int u = 0; u < 8; u++) {
            const int k4 = kb + u;
            ulonglong2 wF = Wsm[(k4 * 3 + 0) * 32 + lane];
            ulonglong2 wO = Wsm[(k4 * 3 + 1) * 32 + lane];
            ulonglong2 wH = Wsm[(k4 * 3 + 2) * 32 + lane];
#pragma unroll
            for (int r = 0; r < 8; r++) {
                ulonglong2 hv = Hsm[r * 64 + k4];
                aF[r] = ffma2(wF.x, hv.x, aF[r]);
                aF[r] = ffma2(wF.y, hv.y, aF[r]);
                aO[r] = ffma2(wO.x, hv.x, aO[r]);
                aO[r] = ffma2(wO.y, hv.y, aO[r]);
                aH[r] = ffma2(wH.x, hv.x, aH[r]);
                aH[r] = ffma2(wH.y, hv.y, aH[r]);
            }
        }
#pragma unroll
        for (int r = 0; r < 8; r++) {
            Gsm[((kq * 3 + 0) * 8 + r) * 32 + lane] = f2sum(aF[r]);
            Gsm[((kq * 3 + 1) * 8 + r) * 32 + lane] = f2sum(aO[r]);
            Gsm[((kq * 3 + 2) * 8 + r) * 32 + lane] = f2sum(aH[r]);
        }
        __syncthreads();   // (A) join for the cross-warp reduction

        // ---- epilogue: reduce 8 partials, gates, C, H_new -------------------
        {
            float gF = gxF, gO = gxO, gH = gxH;
#pragma unroll
            for (int q = 0; q < 8; q++) {
                gF += Gsm[((q * 3 + 0) * 8 + er) * 32 + ej];
                gO += Gsm[((q * 3 + 1) * 8 + er) * 32 + ej];
                gH += Gsm[((q * 3 + 2) * 8 + er) * 32 + ej];
            }
            float F  = sig_fast(gF);
            float O  = sig_fast(gO);
            float Ht = tanh_fast(gH);
            float c  = F * Csm[tid] + O * Ht;      // faithful: uses O, not I
            Csm[tid] = c;
            float hn = O * tanh_fast(c);
            Hstage[er * 32 + ej] = hn;                       // self-slice stage
            __stcg(g_Hbuf[nxt] + (rb + er) * HDIM + j0 + ej, hn);
            if (t == LSEQ - 1)
                out[(rb + er) * HDIM + j0 + ej] = hn;
        }
        __syncthreads();   // (B) stores complete before the release-arrives

        // ---- arrive: one release-arrive on each peer's mbar[ct] -------------
        if (tid < 8 && tid != ct)
            mbar_arrive_rank(sbase + SM_MBAR + (uint32_t)ct * 8, (uint32_t)tid);
    }

    // no CTA may exit while peers could still arrive on its mbarriers
    cluster_sync_();
}

// ---------------------------------------------------------------------------
// launcher
// ---------------------------------------------------------------------------
extern "C" void kernel_launch(void* const* d_in, const int* in_sizes, int n_in,
                              void* d_out, int out_size)
{
    (void)in_sizes; (void)n_in; (void)out_size;
    const void*  X   = d_in[0];
    const float* E   = (const float*)d_in[1];
    const float* Ww  = (const float*)d_in[2];
    const float* Wb  = (const float*)d_in[3];
    float*       out = (float*)d_out;

    cudaFuncSetAttribute(lstm_kernel,
                         cudaFuncAttributeMaxDynamicSharedMemorySize,
                         SMEM_TOTAL);

    table_kernel<<<dim3(VOC / 64, G3 / 64), 256>>>(E, Ww, Wb);
    lstm_kernel<<<128, NT, SMEM_TOTAL>>>(X, Ww, out);
}